// round 16
// baseline (speedup 1.0000x reference)
#include <cuda_runtime.h>
#include <math.h>
#include <stdint.h>

#define N_NODES 10000
#define N_EDGES 80000
#define E_TOT   90000      // edges + self loops
#define IN_DIM  768
#define HID     256
#define HEADS   8
#define F1      (HEADS*HID)   // 2048
#define NEG_SLOPE 0.2f

// ---------------- scratch (static device globals; no allocation) ----------------
__device__ float g_h1  [(size_t)N_NODES * F1];   // x @ W1
__device__ float g_agg1[(size_t)N_NODES * F1];   // layer-1 agg + bias + ELU (tf32-rounded)
__device__ float g_h2  [(size_t)N_NODES * F1];   // agg1 @ W2
__device__ float g_h2m [(size_t)N_NODES * HID];  // layer-2 head-mean + b2 (tf32-rounded)
__device__ float g_as  [N_NODES * HEADS];
__device__ float g_ad  [N_NODES * HEADS];
__device__ float g_m   [N_NODES * HEADS];
__device__ float g_den [N_NODES * HEADS];
__device__ int   g_ei64;                         // 1 if edge_index stored as int64
// tf32-rounded GEMM inputs (rounding at source == rounding at load; no extra error)
__device__ float g_xc  [(size_t)N_NODES * IN_DIM];
__device__ float g_w1c [(size_t)IN_DIM * F1];
__device__ float g_w2c [(size_t)F1 * F1];
__device__ float g_wpc [(size_t)HID * HID];
// CSR by dst
__device__ int   g_deg   [N_NODES];
__device__ int   g_rowptr[N_NODES + 1];
__device__ int   g_cursor[N_NODES];
__device__ int   g_col   [E_TOT];                // src node per CSR slot

__device__ __forceinline__ uint32_t f2tf32(float f) {
    uint32_t u;
    asm("cvt.rna.tf32.f32 %0, %1;" : "=r"(u) : "f"(f));
    return u;
}
__device__ __forceinline__ float tf32r(float f) { return __uint_as_float(f2tf32(f)); }

// ---------------- tf32 pre-round pass (float4) ----------------------------------
__global__ void round_kernel(const float4* __restrict__ src, float4* __restrict__ dst,
                             int n4)
{
    int i = blockIdx.x * blockDim.x + threadIdx.x;
    if (i >= n4) return;
    float4 v = src[i];
    v.x = tf32r(v.x); v.y = tf32r(v.y); v.z = tf32r(v.z); v.w = tf32r(v.w);
    dst[i] = v;
}

// ======================  tf32 mma.sync GEMM (cp.async, BK=32, 2-stage)  ==========
// C[M,N] = A[M,K] @ W[K,N].  CTA 128x128, 4 warps (2x2) of 64x64, BK=32 per stage,
// issue-before-compute double buffer: load of stage s+1 goes into buf^1 (freed by
// compute of s-1, guarded by that iteration's __syncthreads) and completes under
// the ~1000-cycle compute window of stage s.  Requires K % 32 == 0, N % 128 == 0.
__device__ __forceinline__ void mma_tf32(float* c, const uint32_t* a, const uint32_t* b) {
    asm volatile(
        "mma.sync.aligned.m16n8k8.row.col.f32.tf32.tf32.f32 "
        "{%0,%1,%2,%3}, {%4,%5,%6,%7}, {%8,%9}, {%0,%1,%2,%3};"
        : "+f"(c[0]), "+f"(c[1]), "+f"(c[2]), "+f"(c[3])
        : "r"(a[0]), "r"(a[1]), "r"(a[2]), "r"(a[3]), "r"(b[0]), "r"(b[1]));
}

__device__ __forceinline__ void cp_async16(uint32_t saddr, const void* gptr, int srcsz) {
    asm volatile("cp.async.cg.shared.global [%0], [%1], 16, %2;"
                 :: "r"(saddr), "l"(gptr), "r"(srcsz));
}
__device__ __forceinline__ void cp_commit() {
    asm volatile("cp.async.commit_group;");
}
template<int N_>
__device__ __forceinline__ void cp_wait() {
    asm volatile("cp.async.wait_group %0;" :: "n"(N_));
}

#define BKK    32
#define KPAD   36      // A: frag bank = 4*gid+tig (all distinct); 144B rows (16B aligned)
#define NPAD   136     // B: frag bank = 8*tig+gid (all distinct); 544B rows (16B aligned)
#define NSTAGE 2
#define A_STG  (128 * KPAD)          // uint32 per A stage (4608)
#define B_STG  (BKK * NPAD)          // uint32 per B stage (4352)
#define GEMM_SMEM ((NSTAGE * (A_STG + B_STG)) * 4)   // 71680 B; x3 CTAs = 215KB/SM

template<int EPI>   // 0 = plain store, 1 = +bias then relu
__global__ __launch_bounds__(128, 3)
void mma_gemm_kernel(const float* __restrict__ A, const float* __restrict__ W,
                     float* __restrict__ C, int M, int N, int K,
                     const float* __restrict__ bias)
{
    extern __shared__ __align__(16) uint32_t smem[];
    uint32_t* As = smem;                    // [NSTAGE][A_STG]
    uint32_t* Bs = smem + NSTAGE * A_STG;   // [NSTAGE][B_STG]
    uint32_t sA, sB;
    {
        sA = (uint32_t)(uint64_t)__cvta_generic_to_shared(As);
        sB = (uint32_t)(uint64_t)__cvta_generic_to_shared(Bs);
    }

    const int tid  = threadIdx.x;
    const int lane = tid & 31;
    const int wid  = tid >> 5;          // 0..3
    const int gid  = lane >> 2;
    const int tig  = lane & 3;
    const int wm   = (wid & 1) * 64;
    const int wn   = (wid >> 1) * 64;
    const int row0 = blockIdx.y * 128;
    const int col0 = blockIdx.x * 128;

    float acc[4][8][4];
    #pragma unroll
    for (int mt = 0; mt < 4; mt++)
        #pragma unroll
        for (int nt = 0; nt < 8; nt++)
            #pragma unroll
            for (int i = 0; i < 4; i++) acc[mt][nt][i] = 0.f;

    const int S = K / BKK;

    // A: 128 rows x 32 floats = 1024 float4, 8 per thread
    const int ar  = tid >> 3;            // 0..15 (+ it*16)
    const int akq = (tid & 7) * 4;       // float offset within the 32-float k block
    // B: 32 k x 128 n = 1024 float4, 8 per thread
    const int bkk = tid >> 2;            // 0..31
    const int bq  = tid & 3;             // float4 index base

    auto load_stage = [&](int s, int buf) {
        int k0 = s * BKK;
        uint32_t ab = sA + (uint32_t)buf * A_STG * 4;
        #pragma unroll
        for (int it = 0; it < 8; it++) {
            int row = ar + it * 16;
            int sz = (row0 + row < M) ? 16 : 0;      // zero-fill OOB rows
            cp_async16(ab + (uint32_t)(row * KPAD + akq) * 4,
                       A + (size_t)(row0 + row) * K + k0 + akq, sz);
        }
        uint32_t bb = sB + (uint32_t)buf * B_STG * 4;
        #pragma unroll
        for (int it = 0; it < 8; it++) {
            int nq = (bq + it * 4) * 4;              // float offset
            cp_async16(bb + (uint32_t)(bkk * NPAD + nq) * 4,
                       W + (size_t)(k0 + bkk) * N + col0 + nq, 16);
        }
        cp_commit();
    };

    load_stage(0, 0);
    cp_wait<0>();
    __syncthreads();

    for (int s = 0; s < S; s++) {
        int buf = s & 1;
        // Issue next-stage loads into buf^1 BEFORE compute. buf^1 was consumed
        // at iteration s-1 and all warps passed that iteration's barrier.
        if (s + 1 < S) load_stage(s + 1, buf ^ 1);

        const uint32_t* Ab = As + buf * A_STG;
        const uint32_t* Bb = Bs + buf * B_STG;
        #pragma unroll
        for (int kk = 0; kk < 4; kk++) {
            int kb = kk * 8;
            uint32_t b[8][2];
            #pragma unroll
            for (int nt = 0; nt < 8; nt++) {
                int n = wn + nt * 8 + gid;
                b[nt][0] = Bb[(kb + tig)     * NPAD + n];
                b[nt][1] = Bb[(kb + tig + 4) * NPAD + n];
            }
            #pragma unroll
            for (int mt = 0; mt < 4; mt++) {
                int m = wm + mt * 16;
                uint32_t a[4];
                a[0] = Ab[(m + gid)     * KPAD + kb + tig];
                a[1] = Ab[(m + gid + 8) * KPAD + kb + tig];
                a[2] = Ab[(m + gid)     * KPAD + kb + tig + 4];
                a[3] = Ab[(m + gid + 8) * KPAD + kb + tig + 4];
                #pragma unroll
                for (int nt = 0; nt < 8; nt++)
                    mma_tf32(acc[mt][nt], a, b[nt]);
            }
        }

        if (s + 1 < S) cp_wait<0>();
        __syncthreads();
    }

    #pragma unroll
    for (int mt = 0; mt < 4; mt++) {
        int r0 = row0 + wm + mt * 16 + gid;
        int r1 = r0 + 8;
        #pragma unroll
        for (int nt = 0; nt < 8; nt++) {
            int c = col0 + wn + nt * 8 + tig * 2;
            float2 v0 = make_float2(acc[mt][nt][0], acc[mt][nt][1]);
            float2 v1 = make_float2(acc[mt][nt][2], acc[mt][nt][3]);
            if (EPI) {
                float bc0 = bias[c], bc1 = bias[c + 1];
                v0.x = fmaxf(v0.x + bc0, 0.f); v0.y = fmaxf(v0.y + bc1, 0.f);
                v1.x = fmaxf(v1.x + bc0, 0.f); v1.y = fmaxf(v1.y + bc1, 0.f);
            }
            if (r0 < M) *(float2*)(C + (size_t)r0 * N + c) = v0;
            if (r1 < M) *(float2*)(C + (size_t)r1 * N + c) = v1;
        }
    }
}

// ---------------- edge-index dtype detection ------------------------------------
__global__ void detect_kernel(const void* __restrict__ ei)
{
    const long long* p = (const long long*)ei;
    int ok = 1;
    for (int i = 0; i < 64; i++) {
        long long v = p[i];
        if (v < 0 || v >= N_NODES) { ok = 0; break; }
    }
    g_ei64 = ok;
}

__device__ __forceinline__ bool edge_sd(const void* __restrict__ ei,
                                        int e, int& s, int& d)
{
    if (e >= N_EDGES) { s = d = e - N_EDGES; return true; }   // self loop
    if (g_ei64) {
        const long long* p = (const long long*)ei;
        s = (int)p[e];
        d = (int)p[N_EDGES + e];
    } else {
        const int* p = (const int*)ei;
        s = p[e];
        d = p[N_EDGES + e];
    }
    return ((unsigned)s < N_NODES) && ((unsigned)d < N_NODES);
}

// ======================  CSR build (once per launch)  ===========================
__global__ void zero_deg_kernel()
{
    int i = blockIdx.x * blockDim.x + threadIdx.x;
    if (i < N_NODES) g_deg[i] = 0;
}

__global__ void count_kernel(const void* __restrict__ ei)
{
    int e = blockIdx.x * blockDim.x + threadIdx.x;
    if (e >= E_TOT) return;
    int s, d;
    if (!edge_sd(ei, e, s, d)) return;
    atomicAdd(&g_deg[d], 1);
}

// single-block exclusive scan of g_deg -> g_rowptr (+ cursor copy)
__global__ __launch_bounds__(1024)
void scan_kernel()
{
    __shared__ int sa[1024], sb[1024];
    const int CH = (N_NODES + 1023) / 1024;       // 10
    int tid = threadIdx.x;
    int base = tid * CH;
    int local[CH];
    int s = 0;
    #pragma unroll
    for (int i = 0; i < CH; i++) {
        int idx = base + i;
        local[i] = s;
        s += (idx < N_NODES) ? g_deg[idx] : 0;
    }
    sa[tid] = s;
    __syncthreads();
    int* src = sa; int* dst = sb;
    for (int off = 1; off < 1024; off <<= 1) {
        int v = src[tid];
        if (tid >= off) v += src[tid - off];
        dst[tid] = v;
        __syncthreads();
        int* tp = src; src = dst; dst = tp;
    }
    int excl = (tid > 0) ? src[tid - 1] : 0;
    #pragma unroll
    for (int i = 0; i < CH; i++) {
        int idx = base + i;
        if (idx < N_NODES) {
            int v = excl + local[i];
            g_rowptr[idx] = v;
            g_cursor[idx] = v;
        }
    }
    if (tid == 1023) g_rowptr[N_NODES] = src[1023];
}

__global__ void fill_kernel(const void* __restrict__ ei)
{
    int e = blockIdx.x * blockDim.x + threadIdx.x;
    if (e >= E_TOT) return;
    int s, d;
    if (!edge_sd(ei, e, s, d)) return;
    int pos = atomicAdd(&g_cursor[d], 1);
    g_col[pos] = s;
}

// ---------------- per-(node,head) attention logits: one warp each --------------
__global__ __launch_bounds__(256)
void alpha_kernel(const float* __restrict__ h, const float* __restrict__ a_src,
                  const float* __restrict__ a_dst,
                  float* __restrict__ as_o, float* __restrict__ ad_o)
{
    int warp = (blockIdx.x * blockDim.x + threadIdx.x) >> 5;
    int lane = threadIdx.x & 31;
    if (warp >= N_NODES * HEADS) return;
    int n  = warp / HEADS;
    int hd = warp % HEADS;
    const float* hp  = h + (size_t)n * F1 + hd * HID;
    const float* asp = a_src + hd * HID;
    const float* adp = a_dst + hd * HID;
    float s = 0.f, d = 0.f;
    #pragma unroll
    for (int i = lane; i < HID; i += 32) {
        float v = hp[i];
        s = fmaf(v, asp[i], s);
        d = fmaf(v, adp[i], d);
    }
    #pragma unroll
    for (int o = 16; o; o >>= 1) {
        s += __shfl_down_sync(0xffffffffu, s, o);
        d += __shfl_down_sync(0xffffffffu, d, o);
    }
    if (lane == 0) { as_o[warp] = s; ad_o[warp] = d; }
}

// ---------------- CSR softmax stats: one warp per node --------------------------
__global__ __launch_bounds__(256)
void csr_softmax_kernel(const float* __restrict__ as, const float* __restrict__ ad,
                        float* __restrict__ m, float* __restrict__ den)
{
    int warp = (blockIdx.x * blockDim.x + threadIdx.x) >> 5;
    int lane = threadIdx.x & 31;
    if (warp >= N_NODES) return;
    int d    = warp;
    int hd   = lane & 7;
    int slot = lane >> 3;
    int beg = g_rowptr[d], end = g_rowptr[d + 1];
    float adv = ad[d * HEADS + hd];

    float mx = -INFINITY;
    for (int i = beg + slot; i < end; i += 4) {
        float v = as[g_col[i] * HEADS + hd] + adv;
        v = v >= 0.f ? v : NEG_SLOPE * v;
        mx = fmaxf(mx, v);
    }
    mx = fmaxf(mx, __shfl_xor_sync(0xffffffffu, mx, 8));
    mx = fmaxf(mx, __shfl_xor_sync(0xffffffffu, mx, 16));

    float dn = 0.f;
    for (int i = beg + slot; i < end; i += 4) {
        float v = as[g_col[i] * HEADS + hd] + adv;
        v = v >= 0.f ? v : NEG_SLOPE * v;
        dn += expf(v - mx);
    }
    dn += __shfl_xor_sync(0xffffffffu, dn, 8);
    dn += __shfl_xor_sync(0xffffffffu, dn, 16);

    if (slot == 0) {
        m[d * HEADS + hd]   = mx;
        den[d * HEADS + hd] = dn;
    }
}

// ---------------- CSR gather: one CTA per dst node ------------------------------
// 256 threads x 8 channels each. EPI=1: +b1 then ELU -> out[N,2048] (tf32-rounded,
// feeds GEMM2 only). EPI=2: head-mean + b2 -> out[N,256] (tf32-rounded, GEMM3 only).
template<int EPI>
__global__ __launch_bounds__(256)
void gather_kernel(const float* __restrict__ h,
                   const float* __restrict__ as, const float* __restrict__ ad,
                   const float* __restrict__ m, const float* __restrict__ den,
                   const float* __restrict__ bias, float* __restrict__ out)
{
    __shared__ float red[F1];                 // used by EPI=2 only (8 KB)
    int d   = blockIdx.x;
    int tid = threadIdx.x;
    int ch  = tid * 8;
    int hd  = tid >> 5;                       // 256 channels per head
    int beg = g_rowptr[d], end = g_rowptr[d + 1];

    float md  = m[d * HEADS + hd];
    float dn  = den[d * HEADS + hd] + 1e-16f;
    float adv = ad[d * HEADS + hd];
    float inv = 1.f / dn;

    float acc[8];
    #pragma unroll
    for (int i = 0; i < 8; i++) acc[i] = 0.f;

    for (int i = beg; i < end; i++) {
        int s = g_col[i];
        float v = as[s * HEADS + hd] + adv;
        v = v >= 0.f ? v : NEG_SLOPE * v;
        float al = expf(v - md) * inv;
        const float4* hp = (const float4*)(h + (size_t)s * F1 + ch);
        float4 a0 = hp[0], a1 = hp[1];
        acc[0] = fmaf(al, a0.x, acc[0]); acc[1] = fmaf(al, a0.y, acc[1]);
        acc[2] = fmaf(al, a0.z, acc[2]); acc[3] = fmaf(al, a0.w, acc[3]);
        acc[4] = fmaf(al, a1.x, acc[4]); acc[5] = fmaf(al, a1.y, acc[5]);
        acc[6] = fmaf(al, a1.z, acc[6]); acc[7] = fmaf(al, a1.w, acc[7]);
    }

    if (EPI == 1) {
        float* op = out + (size_t)d * F1 + ch;
        #pragma unroll
        for (int j = 0; j < 8; j++) {
            float v = acc[j] + bias[ch + j];
            v = v > 0.f ? v : (expf(v) - 1.f);
            op[j] = tf32r(v);                 // GEMM2 would round on load anyway
        }
    } else {
        #pragma unroll
        for (int j = 0; j < 8; j++) red[ch + j] = acc[j];
        __syncthreads();
        int c = tid;                           // 0..255
        float s = 0.f;
        #pragma unroll
        for (int hh = 0; hh < HEADS; hh++) s += red[hh * HID + c];
        out[(size_t)d * HID + c] = tf32r(s * (1.f / HEADS) + bias[c]);
    }
}

// ---------------- launch ---------------------------------------------------------
extern "C" void kernel_launch(void* const* d_in, const int* in_sizes, int n_in,
                              void* d_out, int out_size)
{
    const float* x      = (const float*)d_in[0];
    const void*  eindex = d_in[1];
    const float* W1     = (const float*)d_in[2];
    const float* a_src1 = (const float*)d_in[3];
    const float* a_dst1 = (const float*)d_in[4];
    const float* b1     = (const float*)d_in[5];
    const float* W2     = (const float*)d_in[6];
    const float* a_src2 = (const float*)d_in[7];
    const float* a_dst2 = (const float*)d_in[8];
    const float* b2     = (const float*)d_in[9];
    const float* Wp     = (const float*)d_in[10];
    const float* bp     = (const float*)d_in[11];
    float*       out    = (float*)d_out;

    float *h1, *agg1, *h2, *h2m, *as, *ad, *m, *den;
    float *xc, *w1c, *w2c, *wpc;
    cudaGetSymbolAddress((void**)&h1,   g_h1);
    cudaGetSymbolAddress((void**)&agg1, g_agg1);
    cudaGetSymbolAddress((void**)&h2,   g_h2);
    cudaGetSymbolAddress((void**)&h2m,  g_h2m);
    cudaGetSymbolAddress((void**)&as,   g_as);
    cudaGetSymbolAddress((void**)&ad,   g_ad);
    cudaGetSymbolAddress((void**)&m,    g_m);
    cudaGetSymbolAddress((void**)&den,  g_den);
    cudaGetSymbolAddress((void**)&xc,   g_xc);
    cudaGetSymbolAddress((void**)&w1c,  g_w1c);
    cudaGetSymbolAddress((void**)&w2c,  g_w2c);
    cudaGetSymbolAddress((void**)&wpc,  g_wpc);

    cudaFuncSetAttribute(mma_gemm_kernel<0>,
                         cudaFuncAttributeMaxDynamicSharedMemorySize, GEMM_SMEM);
    cudaFuncSetAttribute(mma_gemm_kernel<1>,
                         cudaFuncAttributeMaxDynamicSharedMemorySize, GEMM_SMEM);

    const int TB = 256;
    const int MROWS = (N_NODES + 127) / 128;        // 79
    const int SWGRID = (N_NODES * 32 + TB - 1) / TB;

    // tf32 pre-round passes (GEMM-only consumers -> identical math to load-time cvt)
    detect_kernel<<<1, 1>>>(eindex);                                          // 0
    round_kernel<<<(N_NODES * IN_DIM / 4 + TB - 1) / TB, TB>>>((const float4*)x,
                                                               (float4*)xc,
                                                               N_NODES * IN_DIM / 4);  // 1
    round_kernel<<<(IN_DIM * F1 / 4 + TB - 1) / TB, TB>>>((const float4*)W1,
                                                          (float4*)w1c,
                                                          IN_DIM * F1 / 4);  // 2
    mma_gemm_kernel<0><<<dim3(F1 / 128, MROWS), 128, GEMM_SMEM>>>(xc, w1c, h1,   // 3 (ncu slot)
                                                       N_NODES, F1, IN_DIM, nullptr);
    round_kernel<<<(F1 * F1 / 4 + TB - 1) / TB, TB>>>((const float4*)W2,
                                                      (float4*)w2c, F1 * F1 / 4);
    round_kernel<<<(HID * HID / 4 + TB - 1) / TB, TB>>>((const float4*)Wp,
                                                        (float4*)wpc, HID * HID / 4);

    // ---- CSR build (graph is launch-invariant) ----
    zero_deg_kernel<<<(N_NODES + TB - 1) / TB, TB>>>();
    count_kernel<<<(E_TOT + TB - 1) / TB, TB>>>(eindex);
    scan_kernel<<<1, 1024>>>();
    fill_kernel<<<(E_TOT + TB - 1) / TB, TB>>>(eindex);

    // ---- layer 1 (attention) ----
    alpha_kernel<<<(N_NODES * HEADS * 32 + TB - 1) / TB, TB>>>(h1, a_src1, a_dst1, as, ad);
    csr_softmax_kernel<<<SWGRID, TB>>>(as, ad, m, den);
    gather_kernel<1><<<N_NODES, TB>>>(h1, as, ad, m, den, b1, agg1);

    // ---- layer 2 ----
    mma_gemm_kernel<0><<<dim3(F1 / 128, MROWS), 128, GEMM_SMEM>>>(agg1, w2c, h2,
                                                       N_NODES, F1, F1, nullptr);
    alpha_kernel<<<(N_NODES * HEADS * 32 + TB - 1) / TB, TB>>>(h2, a_src2, a_dst2, as, ad);
    csr_softmax_kernel<<<SWGRID, TB>>>(as, ad, m, den);
    gather_kernel<2><<<N_NODES, TB>>>(h2, as, ad, m, den, b2, h2m);

    // ---- projection + relu ----
    mma_gemm_kernel<1><<<dim3(HID / 128, MROWS), 128, GEMM_SMEM>>>(h2m, wpc, out,
                                                        N_NODES, HID, HID, bp);
}

// round 17
// speedup vs baseline: 1.1092x; 1.1092x over previous
#include <cuda_runtime.h>
#include <math.h>
#include <stdint.h>

#define N_NODES 10000
#define N_EDGES 80000
#define E_TOT   90000      // edges + self loops
#define IN_DIM  768
#define HID     256
#define HEADS   8
#define F1      (HEADS*HID)   // 2048
#define NEG_SLOPE 0.2f

// ---------------- scratch (static device globals; no allocation) ----------------
__device__ float g_h1  [(size_t)N_NODES * F1];   // x @ W1
__device__ float g_agg1[(size_t)N_NODES * F1];   // layer-1 agg + bias + ELU (tf32-rounded)
__device__ float g_h2  [(size_t)N_NODES * F1];   // agg1 @ W2
__device__ float g_h2m [(size_t)N_NODES * HID];  // layer-2 head-mean + b2 (tf32-rounded)
__device__ float g_as  [N_NODES * HEADS];
__device__ float g_ad  [N_NODES * HEADS];
__device__ float g_m   [N_NODES * HEADS];
__device__ float g_den [N_NODES * HEADS];
__device__ int   g_ei64;                         // 1 if edge_index stored as int64
// tf32-rounded GEMM inputs (rounding at source == rounding at load; no extra error)
__device__ float g_xc  [(size_t)N_NODES * IN_DIM];
__device__ float g_w1c [(size_t)IN_DIM * F1];
__device__ float g_w2c [(size_t)F1 * F1];
__device__ float g_wpc [(size_t)HID * HID];
// CSR by dst
__device__ int   g_deg   [N_NODES];
__device__ int   g_rowptr[N_NODES + 1];
__device__ int   g_cursor[N_NODES];
__device__ int   g_col   [E_TOT];                // src node per CSR slot

__device__ __forceinline__ uint32_t f2tf32(float f) {
    uint32_t u;
    asm("cvt.rna.tf32.f32 %0, %1;" : "=r"(u) : "f"(f));
    return u;
}
__device__ __forceinline__ float tf32r(float f) { return __uint_as_float(f2tf32(f)); }

// ---------------- tf32 pre-round pass (float4) ----------------------------------
__global__ void round_kernel(const float4* __restrict__ src, float4* __restrict__ dst,
                             int n4)
{
    int i = blockIdx.x * blockDim.x + threadIdx.x;
    if (i >= n4) return;
    float4 v = src[i];
    v.x = tf32r(v.x); v.y = tf32r(v.y); v.z = tf32r(v.z); v.w = tf32r(v.w);
    dst[i] = v;
}

// ======================  tf32 mma.sync GEMM (cp.async, BK=16, 4-stage)  ==========
// C[M,N] = A[M,K] @ W[K,N].  CTA 128x128, 4 warps (2x2) of 64x64, BK=16,
// 4-stage cp.async pipeline issuing 3 stages ahead: the stage consumed next was
// issued 2 iterations ago (~2 compute windows of latency tolerance), and wait<2>
// keeps a slack buffer so the barrier never serializes on the newest loads.
__device__ __forceinline__ void mma_tf32(float* c, const uint32_t* a, const uint32_t* b) {
    asm volatile(
        "mma.sync.aligned.m16n8k8.row.col.f32.tf32.tf32.f32 "
        "{%0,%1,%2,%3}, {%4,%5,%6,%7}, {%8,%9}, {%0,%1,%2,%3};"
        : "+f"(c[0]), "+f"(c[1]), "+f"(c[2]), "+f"(c[3])
        : "r"(a[0]), "r"(a[1]), "r"(a[2]), "r"(a[3]), "r"(b[0]), "r"(b[1]));
}

__device__ __forceinline__ void cp_async16(uint32_t saddr, const void* gptr, int srcsz) {
    asm volatile("cp.async.cg.shared.global [%0], [%1], 16, %2;"
                 :: "r"(saddr), "l"(gptr), "r"(srcsz));
}
__device__ __forceinline__ void cp_commit() {
    asm volatile("cp.async.commit_group;");
}
template<int N_>
__device__ __forceinline__ void cp_wait() {
    asm volatile("cp.async.wait_group %0;" :: "n"(N_));
}

#define BKK    16
#define KPAD   20      // A: conflict-free frag loads; 80B rows (16B aligned)
#define NPAD   136     // B: frag bank = 8*tig+gid, all distinct; 544B rows (16B aligned)
#define NSTAGE 4
#define A_STG  (128 * KPAD)          // uint32 per A stage (2560)
#define B_STG  (BKK * NPAD)          // uint32 per B stage (2176)
#define GEMM_SMEM ((NSTAGE * (A_STG + B_STG)) * 4)   // 75776 B; x3 CTAs = 227.3KB/SM

template<int EPI>   // 0 = plain store, 1 = +bias then relu
__global__ __launch_bounds__(128, 3)
void mma_gemm_kernel(const float* __restrict__ A, const float* __restrict__ W,
                     float* __restrict__ C, int M, int N, int K,
                     const float* __restrict__ bias)
{
    extern __shared__ __align__(16) uint32_t smem[];
    uint32_t* As = smem;                    // [NSTAGE][A_STG]
    uint32_t* Bs = smem + NSTAGE * A_STG;   // [NSTAGE][B_STG]
    uint32_t sA, sB;
    {
        sA = (uint32_t)(uint64_t)__cvta_generic_to_shared(As);
        sB = (uint32_t)(uint64_t)__cvta_generic_to_shared(Bs);
    }

    const int tid  = threadIdx.x;
    const int lane = tid & 31;
    const int wid  = tid >> 5;          // 0..3
    const int gid  = lane >> 2;
    const int tig  = lane & 3;
    const int wm   = (wid & 1) * 64;
    const int wn   = (wid >> 1) * 64;
    const int row0 = blockIdx.y * 128;
    const int col0 = blockIdx.x * 128;

    float acc[4][8][4];
    #pragma unroll
    for (int mt = 0; mt < 4; mt++)
        #pragma unroll
        for (int nt = 0; nt < 8; nt++)
            #pragma unroll
            for (int i = 0; i < 4; i++) acc[mt][nt][i] = 0.f;

    const int S = K / BKK;

    const int ar  = tid >> 2, akq = (tid & 3) * 4;   // A: 4 rows/thread
    const int bkk = tid >> 3, bn  = (tid & 7) * 4;   // B: 4 quads/thread

    auto load_stage = [&](int s, int buf) {
        int k0 = s * BKK;
        uint32_t ab = sA + (uint32_t)buf * A_STG * 4;
        #pragma unroll
        for (int it = 0; it < 4; it++) {
            int row = ar + it * 32;
            int sz = (row0 + row < M) ? 16 : 0;      // zero-fill OOB rows
            cp_async16(ab + (uint32_t)(row * KPAD + akq) * 4,
                       A + (size_t)(row0 + row) * K + k0 + akq, sz);
        }
        uint32_t bb = sB + (uint32_t)buf * B_STG * 4;
        #pragma unroll
        for (int q = 0; q < 4; q++) {
            int nq = bn + q * 32;
            cp_async16(bb + (uint32_t)(bkk * NPAD + nq) * 4,
                       W + (size_t)(k0 + bkk) * N + col0 + nq, 16);
        }
        cp_commit();
    };

    load_stage(0, 0);
    if (1 < S) load_stage(1, 1);
    if (2 < S) load_stage(2, 2);
    cp_wait<2>();                        // stage 0 guaranteed complete
    __syncthreads();

    for (int s = 0; s < S; s++) {
        int buf = s & 3;
        const uint32_t* Ab = As + buf * A_STG;
        const uint32_t* Bb = Bs + buf * B_STG;

        #pragma unroll
        for (int kk = 0; kk < 2; kk++) {
            int kb = kk * 8;
            uint32_t b[8][2];
            #pragma unroll
            for (int nt = 0; nt < 8; nt++) {
                int n = wn + nt * 8 + gid;
                b[nt][0] = Bb[(kb + tig)     * NPAD + n];
                b[nt][1] = Bb[(kb + tig + 4) * NPAD + n];
            }
            #pragma unroll
            for (int mt = 0; mt < 4; mt++) {
                int m = wm + mt * 16;
                uint32_t a[4];
                a[0] = Ab[(m + gid)     * KPAD + kb + tig];
                a[1] = Ab[(m + gid + 8) * KPAD + kb + tig];
                a[2] = Ab[(m + gid)     * KPAD + kb + tig + 4];
                a[3] = Ab[(m + gid + 8) * KPAD + kb + tig + 4];
                #pragma unroll
                for (int nt = 0; nt < 8; nt++)
                    mma_tf32(acc[mt][nt], a, b[nt]);
            }
        }

        // Issue 3 ahead into the buffer freed by compute s-1 (behind its barrier).
        // Tail-adjusted waits guarantee the next consumed stage (s+1) is complete.
        int nx = s + 3;
        if (nx < S)          { load_stage(nx, nx & 3); cp_wait<2>(); }
        else if (s + 2 < S)  { cp_wait<1>(); }
        else if (s + 1 < S)  { cp_wait<0>(); }
        __syncthreads();
    }

    #pragma unroll
    for (int mt = 0; mt < 4; mt++) {
        int r0 = row0 + wm + mt * 16 + gid;
        int r1 = r0 + 8;
        #pragma unroll
        for (int nt = 0; nt < 8; nt++) {
            int c = col0 + wn + nt * 8 + tig * 2;
            float2 v0 = make_float2(acc[mt][nt][0], acc[mt][nt][1]);
            float2 v1 = make_float2(acc[mt][nt][2], acc[mt][nt][3]);
            if (EPI) {
                float bc0 = bias[c], bc1 = bias[c + 1];
                v0.x = fmaxf(v0.x + bc0, 0.f); v0.y = fmaxf(v0.y + bc1, 0.f);
                v1.x = fmaxf(v1.x + bc0, 0.f); v1.y = fmaxf(v1.y + bc1, 0.f);
            }
            if (r0 < M) *(float2*)(C + (size_t)r0 * N + c) = v0;
            if (r1 < M) *(float2*)(C + (size_t)r1 * N + c) = v1;
        }
    }
}

// ---------------- edge-index dtype detection ------------------------------------
__global__ void detect_kernel(const void* __restrict__ ei)
{
    const long long* p = (const long long*)ei;
    int ok = 1;
    for (int i = 0; i < 64; i++) {
        long long v = p[i];
        if (v < 0 || v >= N_NODES) { ok = 0; break; }
    }
    g_ei64 = ok;
}

__device__ __forceinline__ bool edge_sd(const void* __restrict__ ei,
                                        int e, int& s, int& d)
{
    if (e >= N_EDGES) { s = d = e - N_EDGES; return true; }   // self loop
    if (g_ei64) {
        const long long* p = (const long long*)ei;
        s = (int)p[e];
        d = (int)p[N_EDGES + e];
    } else {
        const int* p = (const int*)ei;
        s = p[e];
        d = p[N_EDGES + e];
    }
    return ((unsigned)s < N_NODES) && ((unsigned)d < N_NODES);
}

// ======================  CSR build (once per launch)  ===========================
__global__ void zero_deg_kernel()
{
    int i = blockIdx.x * blockDim.x + threadIdx.x;
    if (i < N_NODES) g_deg[i] = 0;
}

__global__ void count_kernel(const void* __restrict__ ei)
{
    int e = blockIdx.x * blockDim.x + threadIdx.x;
    if (e >= E_TOT) return;
    int s, d;
    if (!edge_sd(ei, e, s, d)) return;
    atomicAdd(&g_deg[d], 1);
}

// single-block exclusive scan of g_deg -> g_rowptr (+ cursor copy)
__global__ __launch_bounds__(1024)
void scan_kernel()
{
    __shared__ int sa[1024], sb[1024];
    const int CH = (N_NODES + 1023) / 1024;       // 10
    int tid = threadIdx.x;
    int base = tid * CH;
    int local[CH];
    int s = 0;
    #pragma unroll
    for (int i = 0; i < CH; i++) {
        int idx = base + i;
        local[i] = s;
        s += (idx < N_NODES) ? g_deg[idx] : 0;
    }
    sa[tid] = s;
    __syncthreads();
    int* src = sa; int* dst = sb;
    for (int off = 1; off < 1024; off <<= 1) {
        int v = src[tid];
        if (tid >= off) v += src[tid - off];
        dst[tid] = v;
        __syncthreads();
        int* tp = src; src = dst; dst = tp;
    }
    int excl = (tid > 0) ? src[tid - 1] : 0;
    #pragma unroll
    for (int i = 0; i < CH; i++) {
        int idx = base + i;
        if (idx < N_NODES) {
            int v = excl + local[i];
            g_rowptr[idx] = v;
            g_cursor[idx] = v;
        }
    }
    if (tid == 1023) g_rowptr[N_NODES] = src[1023];
}

__global__ void fill_kernel(const void* __restrict__ ei)
{
    int e = blockIdx.x * blockDim.x + threadIdx.x;
    if (e >= E_TOT) return;
    int s, d;
    if (!edge_sd(ei, e, s, d)) return;
    int pos = atomicAdd(&g_cursor[d], 1);
    g_col[pos] = s;
}

// ---------------- per-(node,head) attention logits: one warp each --------------
__global__ __launch_bounds__(256)
void alpha_kernel(const float* __restrict__ h, const float* __restrict__ a_src,
                  const float* __restrict__ a_dst,
                  float* __restrict__ as_o, float* __restrict__ ad_o)
{
    int warp = (blockIdx.x * blockDim.x + threadIdx.x) >> 5;
    int lane = threadIdx.x & 31;
    if (warp >= N_NODES * HEADS) return;
    int n  = warp / HEADS;
    int hd = warp % HEADS;
    const float* hp  = h + (size_t)n * F1 + hd * HID;
    const float* asp = a_src + hd * HID;
    const float* adp = a_dst + hd * HID;
    float s = 0.f, d = 0.f;
    #pragma unroll
    for (int i = lane; i < HID; i += 32) {
        float v = hp[i];
        s = fmaf(v, asp[i], s);
        d = fmaf(v, adp[i], d);
    }
    #pragma unroll
    for (int o = 16; o; o >>= 1) {
        s += __shfl_down_sync(0xffffffffu, s, o);
        d += __shfl_down_sync(0xffffffffu, d, o);
    }
    if (lane == 0) { as_o[warp] = s; ad_o[warp] = d; }
}

// ---------------- CSR softmax stats: one warp per node --------------------------
__global__ __launch_bounds__(256)
void csr_softmax_kernel(const float* __restrict__ as, const float* __restrict__ ad,
                        float* __restrict__ m, float* __restrict__ den)
{
    int warp = (blockIdx.x * blockDim.x + threadIdx.x) >> 5;
    int lane = threadIdx.x & 31;
    if (warp >= N_NODES) return;
    int d    = warp;
    int hd   = lane & 7;
    int slot = lane >> 3;
    int beg = g_rowptr[d], end = g_rowptr[d + 1];
    float adv = ad[d * HEADS + hd];

    float mx = -INFINITY;
    for (int i = beg + slot; i < end; i += 4) {
        float v = as[g_col[i] * HEADS + hd] + adv;
        v = v >= 0.f ? v : NEG_SLOPE * v;
        mx = fmaxf(mx, v);
    }
    mx = fmaxf(mx, __shfl_xor_sync(0xffffffffu, mx, 8));
    mx = fmaxf(mx, __shfl_xor_sync(0xffffffffu, mx, 16));

    float dn = 0.f;
    for (int i = beg + slot; i < end; i += 4) {
        float v = as[g_col[i] * HEADS + hd] + adv;
        v = v >= 0.f ? v : NEG_SLOPE * v;
        dn += expf(v - mx);
    }
    dn += __shfl_xor_sync(0xffffffffu, dn, 8);
    dn += __shfl_xor_sync(0xffffffffu, dn, 16);

    if (slot == 0) {
        m[d * HEADS + hd]   = mx;
        den[d * HEADS + hd] = dn;
    }
}

// ---------------- CSR gather: one CTA per dst node ------------------------------
// 256 threads x 8 channels each. EPI=1: +b1 then ELU -> out[N,2048] (tf32-rounded,
// feeds GEMM2 only). EPI=2: head-mean + b2 -> out[N,256] (tf32-rounded, GEMM3 only).
template<int EPI>
__global__ __launch_bounds__(256)
void gather_kernel(const float* __restrict__ h,
                   const float* __restrict__ as, const float* __restrict__ ad,
                   const float* __restrict__ m, const float* __restrict__ den,
                   const float* __restrict__ bias, float* __restrict__ out)
{
    __shared__ float red[F1];                 // used by EPI=2 only (8 KB)
    int d   = blockIdx.x;
    int tid = threadIdx.x;
    int ch  = tid * 8;
    int hd  = tid >> 5;                       // 256 channels per head
    int beg = g_rowptr[d], end = g_rowptr[d + 1];

    float md  = m[d * HEADS + hd];
    float dn  = den[d * HEADS + hd] + 1e-16f;
    float adv = ad[d * HEADS + hd];
    float inv = 1.f / dn;

    float acc[8];
    #pragma unroll
    for (int i = 0; i < 8; i++) acc[i] = 0.f;

    for (int i = beg; i < end; i++) {
        int s = g_col[i];
        float v = as[s * HEADS + hd] + adv;
        v = v >= 0.f ? v : NEG_SLOPE * v;
        float al = expf(v - md) * inv;
        const float4* hp = (const float4*)(h + (size_t)s * F1 + ch);
        float4 a0 = hp[0], a1 = hp[1];
        acc[0] = fmaf(al, a0.x, acc[0]); acc[1] = fmaf(al, a0.y, acc[1]);
        acc[2] = fmaf(al, a0.z, acc[2]); acc[3] = fmaf(al, a0.w, acc[3]);
        acc[4] = fmaf(al, a1.x, acc[4]); acc[5] = fmaf(al, a1.y, acc[5]);
        acc[6] = fmaf(al, a1.z, acc[6]); acc[7] = fmaf(al, a1.w, acc[7]);
    }

    if (EPI == 1) {
        float* op = out + (size_t)d * F1 + ch;
        #pragma unroll
        for (int j = 0; j < 8; j++) {
            float v = acc[j] + bias[ch + j];
            v = v > 0.f ? v : (expf(v) - 1.f);
            op[j] = tf32r(v);                 // GEMM2 would round on load anyway
        }
    } else {
        #pragma unroll
        for (int j = 0; j < 8; j++) red[ch + j] = acc[j];
        __syncthreads();
        int c = tid;                           // 0..255
        float s = 0.f;
        #pragma unroll
        for (int hh = 0; hh < HEADS; hh++) s += red[hh * HID + c];
        out[(size_t)d * HID + c] = tf32r(s * (1.f / HEADS) + bias[c]);
    }
}

// ---------------- launch ---------------------------------------------------------
extern "C" void kernel_launch(void* const* d_in, const int* in_sizes, int n_in,
                              void* d_out, int out_size)
{
    const float* x      = (const float*)d_in[0];
    const void*  eindex = d_in[1];
    const float* W1     = (const float*)d_in[2];
    const float* a_src1 = (const float*)d_in[3];
    const float* a_dst1 = (const float*)d_in[4];
    const float* b1     = (const float*)d_in[5];
    const float* W2     = (const float*)d_in[6];
    const float* a_src2 = (const float*)d_in[7];
    const float* a_dst2 = (const float*)d_in[8];
    const float* b2     = (const float*)d_in[9];
    const float* Wp     = (const float*)d_in[10];
    const float* bp     = (const float*)d_in[11];
    float*       out    = (float*)d_out;

    float *h1, *agg1, *h2, *h2m, *as, *ad, *m, *den;
    float *xc, *w1c, *w2c, *wpc;
    cudaGetSymbolAddress((void**)&h1,   g_h1);
    cudaGetSymbolAddress((void**)&agg1, g_agg1);
    cudaGetSymbolAddress((void**)&h2,   g_h2);
    cudaGetSymbolAddress((void**)&h2m,  g_h2m);
    cudaGetSymbolAddress((void**)&as,   g_as);
    cudaGetSymbolAddress((void**)&ad,   g_ad);
    cudaGetSymbolAddress((void**)&m,    g_m);
    cudaGetSymbolAddress((void**)&den,  g_den);
    cudaGetSymbolAddress((void**)&xc,   g_xc);
    cudaGetSymbolAddress((void**)&w1c,  g_w1c);
    cudaGetSymbolAddress((void**)&w2c,  g_w2c);
    cudaGetSymbolAddress((void**)&wpc,  g_wpc);

    cudaFuncSetAttribute(mma_gemm_kernel<0>,
                         cudaFuncAttributeMaxDynamicSharedMemorySize, GEMM_SMEM);
    cudaFuncSetAttribute(mma_gemm_kernel<1>,
                         cudaFuncAttributeMaxDynamicSharedMemorySize, GEMM_SMEM);

    const int TB = 256;
    const int MROWS = (N_NODES + 127) / 128;        // 79
    const int SWGRID = (N_NODES * 32 + TB - 1) / TB;

    // tf32 pre-round passes (GEMM-only consumers -> identical math to load-time cvt)
    detect_kernel<<<1, 1>>>(eindex);                                          // 0
    round_kernel<<<(N_NODES * IN_DIM / 4 + TB - 1) / TB, TB>>>((const float4*)x,
                                                               (float4*)xc,
                                                               N_NODES * IN_DIM / 4);  // 1
    round_kernel<<<(IN_DIM * F1 / 4 + TB - 1) / TB, TB>>>((const float4*)W1,
                                                          (float4*)w1c,
                                                          IN_DIM * F1 / 4);  // 2
    mma_gemm_kernel<0><<<dim3(F1 / 128, MROWS), 128, GEMM_SMEM>>>(xc, w1c, h1,   // 3 (ncu slot)
                                                       N_NODES, F1, IN_DIM, nullptr);
    round_kernel<<<(F1 * F1 / 4 + TB - 1) / TB, TB>>>((const float4*)W2,
                                                      (float4*)w2c, F1 * F1 / 4);
    round_kernel<<<(HID * HID / 4 + TB - 1) / TB, TB>>>((const float4*)Wp,
                                                        (float4*)wpc, HID * HID / 4);

    // ---- CSR build (graph is launch-invariant) ----
    zero_deg_kernel<<<(N_NODES + TB - 1) / TB, TB>>>();
    count_kernel<<<(E_TOT + TB - 1) / TB, TB>>>(eindex);
    scan_kernel<<<1, 1024>>>();
    fill_kernel<<<(E_TOT + TB - 1) / TB, TB>>>(eindex);

    // ---- layer 1 (attention) ----
    alpha_kernel<<<(N_NODES * HEADS * 32 + TB - 1) / TB, TB>>>(h1, a_src1, a_dst1, as, ad);
    csr_softmax_kernel<<<SWGRID, TB>>>(as, ad, m, den);
    gather_kernel<1><<<N_NODES, TB>>>(h1, as, ad, m, den, b1, agg1);

    // ---- layer 2 ----
    mma_gemm_kernel<0><<<dim3(F1 / 128, MROWS), 128, GEMM_SMEM>>>(agg1, w2c, h2,
                                                       N_NODES, F1, F1, nullptr);
    alpha_kernel<<<(N_NODES * HEADS * 32 + TB - 1) / TB, TB>>>(h2, a_src2, a_dst2, as, ad);
    csr_softmax_kernel<<<SWGRID, TB>>>(as, ad, m, den);
    gather_kernel<2><<<N_NODES, TB>>>(h2, as, ad, m, den, b2, h2m);

    // ---- projection + relu ----
    mma_gemm_kernel<1><<<dim3(HID / 128, MROWS), 128, GEMM_SMEM>>>(h2m, wpc, out,
                                                        N_NODES, HID, HID, bp);
}